// round 7
// baseline (speedup 1.0000x reference)
#include <cuda_runtime.h>
#include <cuda_bf16.h>
#include <cstdint>

// Problem constants
#define NUM_CHIPS 4
#define SEQ 1024
#define HIDDEN 2048
#define TOP_K 4
#define N_EXPERTS 32
#define MAX_TOK 1024
#define META_LEN 8
#define N_PER_CHIP (SEQ * TOP_K)           // 4096
#define N_TOTAL (NUM_CHIPS * N_PER_CHIP)   // 16384 assignments
#define N_CHUNKS (N_TOTAL / 32)            // 512 warp-chunks, chip-major
#define TOTAL_SLOTS (N_EXPERTS * MAX_TOK)  // 32768
#define BUF_ELEMS ((size_t)TOTAL_SLOTS * HIDDEN)
#define META_OFF  BUF_ELEMS
#define CNT_OFF   (BUF_ELEMS + (size_t)TOTAL_SLOTS * META_LEN)

#define PLAN_BLOCKS 16
#define THREADS 512
#define WARPS_PB (THREADS / 32)            // 16 warps/block
#define CHUNKS_PW 2                        // 16 blocks * 16 warps * 2 = 512 chunks

// Scratch (no allocations allowed). All counters are MONOTONE across graph
// replays -> no reset needed, replay-safe.
__device__ int g_src[TOTAL_SLOTS];              // slot -> assignment id (first cnt_e valid)
__device__ int g_cnt[N_EXPERTS];                // per-expert totals
__device__ int g_wcount[N_EXPERTS][N_CHUNKS];   // chunk counts -> (in place) offsets
__device__ unsigned g_pbar;                     // planner barrier tickets
__device__ unsigned g_done;                     // planner completions (+16 per replay)
__device__ unsigned g_sb;                       // slot-block tickets (+32768 per replay)

// Monotone-window barrier among the PLAN_BLOCKS planner blocks (all resident
// in wave 1). Each invocation consumes a window of PLAN_BLOCKS tickets.
__device__ __forceinline__ void planner_bar() {
    __shared__ unsigned target;
    __syncthreads();
    __threadfence();
    if (threadIdx.x == 0) {
        unsigned t = atomicAdd(&g_pbar, 1u);
        target = (t | (PLAN_BLOCKS - 1u)) + 1u;
    }
    __syncthreads();
    if (threadIdx.x == 0)
        while (atomicAdd(&g_pbar, 0u) < target) { }
    __syncthreads();
    __threadfence();
}

__global__ void __launch_bounds__(THREADS) dispatch_kernel(
    const float* __restrict__ x, const float* __restrict__ w,
    const int* __restrict__ idx, float* __restrict__ out)
{
    // ---------------- Planner blocks (bid 0..15, scheduled first) ----------
    if (blockIdx.x < PLAN_BLOCKS) {
        const int warp = threadIdx.x >> 5;
        const int lane = threadIdx.x & 31;
        const unsigned lt = (1u << lane) - 1u;

        // Phase 1: per-chunk expert counts + stable within-chunk rank.
        int ev[CHUNKS_PW], rk[CHUNKS_PW];
#pragma unroll
        for (int j = 0; j < CHUNKS_PW; j++) {
            const int ch = (blockIdx.x * WARPS_PB + warp) * CHUNKS_PW + j;
            g_wcount[lane][ch] = 0;                 // zero this chunk's expert column
            __syncwarp();
            const int e = __ldg(&idx[ch * 32 + lane]);
            const unsigned m = __match_any_sync(0xFFFFFFFFu, e);
            const int r = __popc(m & lt);
            if (r == 0) g_wcount[e][ch] = __popc(m);
            ev[j] = e; rk[j] = r;
        }

        planner_bar();

        // Phase 2: block 0 scans each expert's 512 chunk counts in place.
        // 16 warps -> warp handles 2 experts; lane owns 16 contiguous chunks.
        if (blockIdx.x == 0) {
#pragma unroll
            for (int k = 0; k < 2; k++) {
                const int e = warp * 2 + k;
                const int4* wc = reinterpret_cast<const int4*>(&g_wcount[e][lane * 16]);
                int4 c0 = wc[0], c1 = wc[1], c2 = wc[2], c3 = wc[3];
                int cnt[16] = {c0.x,c0.y,c0.z,c0.w, c1.x,c1.y,c1.z,c1.w,
                               c2.x,c2.y,c2.z,c2.w, c3.x,c3.y,c3.z,c3.w};
                int lsum = 0;
#pragma unroll
                for (int j = 0; j < 16; j++) lsum += cnt[j];
                int s = lsum;
#pragma unroll
                for (int d = 1; d < 32; d <<= 1) {
                    int t = __shfl_up_sync(0xFFFFFFFFu, s, d);
                    if (lane >= d) s += t;
                }
                int run = s - lsum;
                const int total = __shfl_sync(0xFFFFFFFFu, s, 31);
                int ov[16];
#pragma unroll
                for (int j = 0; j < 16; j++) { ov[j] = run; run += cnt[j]; }
                int4* wo = reinterpret_cast<int4*>(&g_wcount[e][lane * 16]);
                wo[0] = make_int4(ov[0],  ov[1],  ov[2],  ov[3]);
                wo[1] = make_int4(ov[4],  ov[5],  ov[6],  ov[7]);
                wo[2] = make_int4(ov[8],  ov[9],  ov[10], ov[11]);
                wo[3] = make_int4(ov[12], ov[13], ov[14], ov[15]);
                if (lane == 0) {
                    g_cnt[e] = total;
                    out[CNT_OFF + e] = (float)total;
                }
            }
        }

        planner_bar();

        // Phase 3: replay register-held (expert, rank) -> inverse map.
#pragma unroll
        for (int j = 0; j < CHUNKS_PW; j++) {
            const int ch = (blockIdx.x * WARPS_PB + warp) * CHUNKS_PW + j;
            const int slot = ev[j] * MAX_TOK + g_wcount[ev[j]][ch] + rk[j];
            g_src[slot] = ch * 32 + lane;
        }
        __threadfence();
        __syncthreads();
        if (threadIdx.x == 0) atomicAdd(&g_done, 1u);   // release: +16 total/replay
        return;
    }

    // ---------------- Slot blocks -----------------------------------------
    const int slot = blockIdx.x - PLAN_BLOCKS;
    if (threadIdx.x == 0) {
        // Monotone ticket -> replay epoch (exactly 32768 slot blocks/replay).
        const unsigned t2  = atomicAdd(&g_sb, 1u);
        const unsigned tgt = ((t2 >> 15) + 1u) * PLAN_BLOCKS;
        while (atomicAdd(&g_done, 0u) < tgt) __nanosleep(64);
        __threadfence();
    }
    __syncthreads();   // also a compiler memory barrier: loads below stay below

    const int e  = slot >> 10;
    const int si = slot & (MAX_TOK - 1);
    const int t  = threadIdx.x;
    float4* dst = reinterpret_cast<float4*>(out + (size_t)slot * HIDDEN);
    float4* md  = reinterpret_cast<float4*>(out + META_OFF + (size_t)slot * META_LEN);

    if (si < g_cnt[e]) {
        const int a   = g_src[slot];
        const int c   = a >> 12;
        const int n   = a & (N_PER_CHIP - 1);
        const int tok = n >> 2;
        const float4* src =
            reinterpret_cast<const float4*>(x + ((size_t)c * SEQ + tok) * HIDDEN);
        dst[t] = src[t];                       // 512 threads x 16B = one 8KB row
        if (t == 0) {
            __nv_bfloat16 hb = __float2bfloat16(w[a]);
            unsigned short bits = __bfloat16_as_ushort(hb);
            md[0] = make_float4((float)c, (float)tok, (float)(n & 3), (float)e);
            md[1] = make_float4((float)bits, 0.f, 0.f, 0.f);
        }
    } else {
        dst[t] = make_float4(0.f, 0.f, 0.f, 0.f);
        if (t == 0) {
            const float4 neg = make_float4(-1.f, -1.f, -1.f, -1.f);
            md[0] = neg;
            md[1] = neg;
        }
    }
}

// ---------------------------------------------------------------------------
extern "C" void kernel_launch(void* const* d_in, const int* in_sizes, int n_in,
                              void* d_out, int out_size) {
    const float* x   = (const float*)d_in[0];   // [4,1024,2048] f32
    const float* wts = (const float*)d_in[1];   // [4,1024,4]    f32
    const int*   ind = (const int*)  d_in[2];   // [4,1024,4]    i32
    float* out = (float*)d_out;

    dispatch_kernel<<<PLAN_BLOCKS + TOTAL_SLOTS, THREADS>>>(x, wts, ind, out);
}

// round 8
// speedup vs baseline: 1.8202x; 1.8202x over previous
#include <cuda_runtime.h>
#include <cuda_bf16.h>
#include <cstdint>

// Problem constants
#define NUM_CHIPS 4
#define SEQ 1024
#define HIDDEN 2048
#define TOP_K 4
#define N_EXPERTS 32
#define MAX_TOK 1024
#define META_LEN 8
#define N_PER_CHIP (SEQ * TOP_K)           // 4096
#define N_TOTAL (NUM_CHIPS * N_PER_CHIP)   // 16384 assignments
#define N_CHUNKS (N_TOTAL / 32)            // 512 warp-chunks, chip-major
#define TOTAL_SLOTS (N_EXPERTS * MAX_TOK)  // 32768
#define BUF_ELEMS ((size_t)TOTAL_SLOTS * HIDDEN)
#define META_OFF  BUF_ELEMS
#define CNT_OFF   (BUF_ELEMS + (size_t)TOTAL_SLOTS * META_LEN)

#define PLAN_BLOCKS 16

// Scratch (no allocations allowed). Barrier counter is MONOTONE across graph
// replays -> no reset kernel needed, replay-safe.
__device__ int g_src[TOTAL_SLOTS];               // slot -> assignment id (first cnt_e valid)
__device__ int g_cnt[N_EXPERTS];                 // per-expert totals
__device__ int g_wcount[N_EXPERTS][N_CHUNKS];    // chunk counts -> (in place) chunk offsets
__device__ unsigned g_pbar;                      // planner barrier tickets (monotone)

// Monotone-window barrier among the PLAN_BLOCKS planner blocks (all resident).
// nanosleep backoff: keeps the LTS quiet and avoids dragging DVFS down while
// idle-waiting.
__device__ __forceinline__ void planner_bar() {
    __shared__ unsigned target;
    __syncthreads();
    __threadfence();
    if (threadIdx.x == 0) {
        unsigned t = atomicAdd(&g_pbar, 1u);
        target = (t | (PLAN_BLOCKS - 1u)) + 1u;
    }
    __syncthreads();
    if (threadIdx.x == 0)
        while (atomicAdd(&g_pbar, 0u) < target) __nanosleep(32);
    __syncthreads();
    __threadfence();
}

// ---------------------------------------------------------------------------
// Planning: 16 blocks x 1024 threads; ranks stay in registers across phases.
// ---------------------------------------------------------------------------
__global__ void __launch_bounds__(1024) plan_kernel(const int* __restrict__ idx,
                                                    float* __restrict__ out) {
    const int warp  = threadIdx.x >> 5;
    const int lane  = threadIdx.x & 31;
    const int chunk = blockIdx.x * 32 + warp;      // 0..511, chip-major
    const int a     = chunk * 32 + lane;           // assignment id

    // Phase 1: per-chunk expert counts + stable within-chunk rank.
    g_wcount[lane][chunk] = 0;
    __syncwarp();
    const int e = idx[a];
    const unsigned m = __match_any_sync(0xFFFFFFFFu, e);
    const int rk = __popc(m & ((1u << lane) - 1u));
    if (rk == 0) g_wcount[e][chunk] = __popc(m);

    planner_bar();

    // Phase 2: block 0 scans each expert's 512 chunk counts in place.
    // Warp e handles expert e; lane owns 16 contiguous chunks (two-level scan).
    if (blockIdx.x == 0) {
        const int ex = warp;
        const int4* wc = reinterpret_cast<const int4*>(&g_wcount[ex][lane * 16]);
        int4 c0 = wc[0], c1 = wc[1], c2 = wc[2], c3 = wc[3];
        int cnt[16] = {c0.x,c0.y,c0.z,c0.w, c1.x,c1.y,c1.z,c1.w,
                       c2.x,c2.y,c2.z,c2.w, c3.x,c3.y,c3.z,c3.w};
        int lsum = 0;
#pragma unroll
        for (int j = 0; j < 16; j++) lsum += cnt[j];
        int s = lsum;
#pragma unroll
        for (int d = 1; d < 32; d <<= 1) {
            int t = __shfl_up_sync(0xFFFFFFFFu, s, d);
            if (lane >= d) s += t;
        }
        int run = s - lsum;
        const int total = __shfl_sync(0xFFFFFFFFu, s, 31);
        int ov[16];
#pragma unroll
        for (int j = 0; j < 16; j++) { ov[j] = run; run += cnt[j]; }
        int4* wo = reinterpret_cast<int4*>(&g_wcount[ex][lane * 16]);
        wo[0] = make_int4(ov[0],  ov[1],  ov[2],  ov[3]);
        wo[1] = make_int4(ov[4],  ov[5],  ov[6],  ov[7]);
        wo[2] = make_int4(ov[8],  ov[9],  ov[10], ov[11]);
        wo[3] = make_int4(ov[12], ov[13], ov[14], ov[15]);
        if (lane == 0) {
            g_cnt[ex] = total;
            out[CNT_OFF + ex] = (float)total;
        }
    }

    planner_bar();

    // Phase 3: replay register-held (expert, rank) -> inverse map.
    const int slot = e * MAX_TOK + g_wcount[e][chunk] + rk;
    g_src[slot] = a;
}

// ---------------------------------------------------------------------------
// Gather: one block per slot; copy token row (or zeros) + 8 meta words.
// Proven fast path: plain float4 stores, 256 threads.
// ---------------------------------------------------------------------------
__global__ void __launch_bounds__(256) gather_kernel(const float* __restrict__ x,
                                                     const float* __restrict__ w,
                                                     float* __restrict__ out) {
    const int slot = blockIdx.x;
    const int e    = slot >> 10;
    const int si   = slot & (MAX_TOK - 1);
    const int t    = threadIdx.x;
    float4* dst = reinterpret_cast<float4*>(out + (size_t)slot * HIDDEN);
    float4* md  = reinterpret_cast<float4*>(out + META_OFF + (size_t)slot * META_LEN);

    if (si < g_cnt[e]) {
        const int a   = g_src[slot];
        const int c   = a >> 12;
        const int n   = a & (N_PER_CHIP - 1);
        const int tok = n >> 2;
        const float4* src =
            reinterpret_cast<const float4*>(x + ((size_t)c * SEQ + tok) * HIDDEN);
        float4 v0 = src[t];
        float4 v1 = src[t + 256];
        dst[t]       = v0;
        dst[t + 256] = v1;
        if (t == 0) {
            __nv_bfloat16 hb = __float2bfloat16(w[a]);
            unsigned short bits = __bfloat16_as_ushort(hb);
            md[0] = make_float4((float)c, (float)tok, (float)(n & 3), (float)e);
            md[1] = make_float4((float)bits, 0.f, 0.f, 0.f);
        }
    } else {
        const float4 z = make_float4(0.f, 0.f, 0.f, 0.f);
        dst[t]       = z;
        dst[t + 256] = z;
        if (t == 0) {
            const float4 neg = make_float4(-1.f, -1.f, -1.f, -1.f);
            md[0] = neg;
            md[1] = neg;
        }
    }
}

// ---------------------------------------------------------------------------
extern "C" void kernel_launch(void* const* d_in, const int* in_sizes, int n_in,
                              void* d_out, int out_size) {
    const float* x   = (const float*)d_in[0];   // [4,1024,2048] f32
    const float* wts = (const float*)d_in[1];   // [4,1024,4]    f32
    const int*   ind = (const int*)  d_in[2];   // [4,1024,4]    i32
    float* out = (float*)d_out;

    plan_kernel<<<PLAN_BLOCKS, 1024>>>(ind, out);
    gather_kernel<<<TOTAL_SLOTS, 256>>>(x, wts, out);
}